// round 9
// baseline (speedup 1.0000x reference)
#include <cuda_runtime.h>
#include <cstdint>

// ---------------------------------------------------------------------------
// Problem constants
// ---------------------------------------------------------------------------
#define NB    4096      // batch
#define DIN   2048
#define HH    1024
#define DD    256       // latent dim == HW
#define NSTEP 15
#define S     16        // samples per trace CTA
#define HS    8         // samples per thread (one half)
#define TPB   512       // trace threads per block

// ---------------------------------------------------------------------------
// Scratch (device globals; no allocation allowed)
// ---------------------------------------------------------------------------
__device__ float g_H   [2 * NB * HH];
__device__ float g_Z   [2 * NB * DD];   // z_s rows 0..4095, z_e rows 4096..8191
__device__ float g_HW  [NB * DD];
__device__ float g_V   [NB * DD];
__device__ float g_WpT [DD * DD];
__device__ float g_mind[NB];

// ---------------------------------------------------------------------------
// Packed fp32x2 helpers (FFMA2 — only reachable via PTX)
// ---------------------------------------------------------------------------
__device__ __forceinline__ unsigned long long pack2(float x, float y) {
    unsigned long long r;
    asm("mov.b64 %0, {%1, %2};" : "=l"(r) : "f"(x), "f"(y));
    return r;
}
__device__ __forceinline__ float2 unpack2(unsigned long long v) {
    float2 r;
    asm("mov.b64 {%0, %1}, %2;" : "=f"(r.x), "=f"(r.y) : "l"(v));
    return r;
}
__device__ __forceinline__ unsigned long long fma2(unsigned long long a,
                                                   unsigned long long b,
                                                   unsigned long long c) {
    unsigned long long d;
    asm("fma.rn.f32x2 %0, %1, %2, %3;" : "=l"(d) : "l"(a), "l"(b), "l"(c));
    return d;
}

// ---------------------------------------------------------------------------
// SGEMM (R4 tile config): C[z][M,N] = act(A_z[M,K] @ B[K,N] + bias[N]).
// BM=BN=128, BK=16, 256 threads, 8x8/thread, double-buffered smem.
// gridDim.z selects A (A0/A1), offsets C by z*M*N.
// ---------------------------------------------------------------------------
#define ASTRIDE 132

template <int ACT>
__global__ __launch_bounds__(256)
void sgemm_kernel(const float* __restrict__ A0, const float* __restrict__ A1,
                  const float* __restrict__ Bm,
                  const float* __restrict__ bias, float* __restrict__ C,
                  int M, int N, int K) {
    __shared__ __align__(16) float As[2 * 16 * ASTRIDE];
    __shared__ __align__(16) float Bs[2 * 16 * 128];

    const float* A = blockIdx.z ? A1 : A0;
    float* Cz = C + (size_t)blockIdx.z * M * N;

    const int tid  = threadIdx.x;
    const int brow = blockIdx.y * 128;
    const int bcol = blockIdx.x * 128;
    const int ty   = tid >> 4;
    const int tx   = tid & 15;

    const int arow = tid >> 1;
    const int acol = (tid & 1) * 8;
    const int br0  = tid >> 5;
    const int bcl  = (tid & 31) * 4;

    const float* Aptr = A  + (size_t)(brow + arow) * K + acol;
    const float* Bptr = Bm + (size_t)br0 * N + bcol + bcl;

    unsigned long long c2[8][4];
#pragma unroll
    for (int m = 0; m < 8; m++)
#pragma unroll
        for (int j = 0; j < 4; j++) c2[m][j] = 0ull;

    float4 a_rg0, a_rg1, b_rg0, b_rg1;

    a_rg0 = *(const float4*)(Aptr + 0);
    a_rg1 = *(const float4*)(Aptr + 4);
    b_rg0 = *(const float4*)(Bptr);
    b_rg1 = *(const float4*)(Bptr + (size_t)8 * N);
    {
        float am[8] = {a_rg0.x, a_rg0.y, a_rg0.z, a_rg0.w,
                       a_rg1.x, a_rg1.y, a_rg1.z, a_rg1.w};
#pragma unroll
        for (int c = 0; c < 8; c++) As[(acol + c) * ASTRIDE + arow] = am[c];
        *(float4*)&Bs[br0 * 128 + bcl]       = b_rg0;
        *(float4*)&Bs[(br0 + 8) * 128 + bcl] = b_rg1;
    }
    __syncthreads();

    int buf = 0;
    const int nblk = K / 16;
    for (int kb = 0; kb < nblk; kb++) {
        const bool has_next = (kb + 1 < nblk);
        if (has_next) {
            const int k0 = (kb + 1) * 16;
            a_rg0 = *(const float4*)(Aptr + k0);
            a_rg1 = *(const float4*)(Aptr + k0 + 4);
            b_rg0 = *(const float4*)(Bptr + (size_t)k0 * N);
            b_rg1 = *(const float4*)(Bptr + (size_t)(k0 + 8) * N);
        }

        const float* Asb = As + buf * 16 * ASTRIDE;
        const float* Bsb = Bs + buf * 16 * 128;
#pragma unroll
        for (int kk = 0; kk < 16; kk++) {
            float4 a0 = *(const float4*)&Asb[kk * ASTRIDE + ty * 8];
            float4 a1 = *(const float4*)&Asb[kk * ASTRIDE + ty * 8 + 4];
            const unsigned long long* brow2 =
                (const unsigned long long*)&Bsb[kk * 128 + tx * 8];
            unsigned long long b2[4];
#pragma unroll
            for (int j = 0; j < 4; j++) b2[j] = brow2[j];
            float am[8] = {a0.x, a0.y, a0.z, a0.w, a1.x, a1.y, a1.z, a1.w};
#pragma unroll
            for (int m = 0; m < 8; m++) {
                unsigned long long aa = pack2(am[m], am[m]);
#pragma unroll
                for (int j = 0; j < 4; j++) c2[m][j] = fma2(aa, b2[j], c2[m][j]);
            }
        }

        if (has_next) {
            float* Asn = As + (buf ^ 1) * 16 * ASTRIDE;
            float* Bsn = Bs + (buf ^ 1) * 16 * 128;
            float am[8] = {a_rg0.x, a_rg0.y, a_rg0.z, a_rg0.w,
                           a_rg1.x, a_rg1.y, a_rg1.z, a_rg1.w};
#pragma unroll
            for (int c = 0; c < 8; c++) Asn[(acol + c) * ASTRIDE + arow] = am[c];
            *(float4*)&Bsn[br0 * 128 + bcl]       = b_rg0;
            *(float4*)&Bsn[(br0 + 8) * 128 + bcl] = b_rg1;
            __syncthreads();
            buf ^= 1;
        }
    }

#pragma unroll
    for (int m = 0; m < 8; m++) {
        const int row = brow + ty * 8 + m;
        float* crow = Cz + (size_t)row * N + bcol + tx * 8;
#pragma unroll
        for (int j = 0; j < 4; j++) {
            float2 p = unpack2(c2[m][j]);
            const int n = bcol + tx * 8 + 2 * j;
            p.x += bias[n];
            p.y += bias[n + 1];
            if (ACT) { p.x = tanhf(p.x); p.y = tanhf(p.y); }
            *(float2*)&crow[2 * j] = p;
        }
    }
}

// ---------------------------------------------------------------------------
// Fused prep: blocks [0,256) transpose Wp1; blocks [256,256+NB) do the
// degenerate-wind fallback. One launch keeps the trace at launch index 5.
// ---------------------------------------------------------------------------
__global__ void prep_kernel(const float* __restrict__ Wp1, float* __restrict__ WpT,
                            float* __restrict__ V, const float* __restrict__ noise) {
    const int b = blockIdx.x;
    const int t = threadIdx.x;
    if (b < DD) {
        WpT[t * DD + b] = Wp1[b * DD + t];
        return;
    }
    const int s = b - DD;
    __shared__ float rw[8], rn[8];
    const int lane = t & 31, warp = t >> 5;
    float w = V[s * DD + t];
    float n = noise[s * DD + t];
    float pw = w * w, pn = n * n;
#pragma unroll
    for (int off = 16; off > 0; off >>= 1) {
        pw += __shfl_xor_sync(0xffffffffu, pw, off);
        pn += __shfl_xor_sync(0xffffffffu, pn, off);
    }
    if (lane == 0) { rw[warp] = pw; rn[warp] = pn; }
    __syncthreads();
    float sw = 0.f, sn = 0.f;
#pragma unroll
    for (int i = 0; i < 8; i++) { sw += rw[i]; sn += rn[i]; }
    float wn = sqrtf(sw + 1e-24f);
    if (wn < 1e-5f) {
        float nn = sqrtf(sn + 1e-24f);
        V[s * DD + t] = w + n / (nn + 1e-12f) * 1e-4f;
    }
}

// ---------------------------------------------------------------------------
// Trace kernel v5: 512 threads/CTA, 16 samples/CTA, thread = (dim, half):
// dim d = t&255, half = t>>8 handles samples [half*8, half*8+8).
// Doubles warps/SMSP vs v2 (6.9 avg) at identical CTA count, L2 traffic and
// reduction trees. Per-thread: 4 f32x2 accumulators, 8-row weight blocks with
// one-block lookahead. State in smem private columns (stride 17, conflict-free).
// Dynamic smem (floats):
//   xt[4096]|sv[4096]  (stride 16, matvec broadcast reads)
//   xs[4352]|vs[4352]|xa[4352]|va[4352]  (stride 17, private)
//   red_a[256]|red_b[256]|bc_a[16]|bc_b[16]
// ---------------------------------------------------------------------------
#define TR_SMEM_FLOATS (2 * 4096 + 4 * 4352 + 256 + 256 + 16 + 16)
#define TR_SMEM_BYTES  (TR_SMEM_FLOATS * 4)

__global__ __launch_bounds__(TPB)
void trace_kernel(const float* __restrict__ Z,    // [8192,256]: z_s | z_e
                  const float* __restrict__ V,    // [4096,256]
                  const float* __restrict__ Wp1,  // [256,256]
                  const float* __restrict__ WpT,  // transposed
                  const float* __restrict__ bp1,
                  const float* __restrict__ wp2,
                  float* __restrict__ mind) {
    extern __shared__ __align__(16) float dsm[];
    float* xt_sm = dsm;                    // [d*16 + s]
    float* sv_sm = dsm + 4096;             // [d*16 + s]
    float* xs_sm = dsm + 8192;             // [d*17 + s]
    float* vs_sm = dsm + 8192 + 4352;      // [d*17 + s]
    float* xa_sm = dsm + 8192 + 2 * 4352;  // [d*17 + s]
    float* va_sm = dsm + 8192 + 3 * 4352;  // [d*17 + s]
    float* red_a = dsm + 8192 + 4 * 4352;          // [16 warps][16 samples]
    float* red_b = red_a + 256;
    float* bc_a  = red_b + 256;            // [16]
    float* bc_b  = bc_a + 16;              // [16]

    const int t    = threadIdx.x;          // 0..511
    const int d    = t & 255;              // output dim
    const int half = t >> 8;               // 0 or 1
    const int sb   = half * HS;            // sample base
    const int lane = t & 31;
    const int warp = t >> 5;               // 0..15
    const int s0   = blockIdx.x * S;
    const float hstep = 1.0f / 15.0f;
    const float bp = bp1[d];
    const float w2 = wp2[d];

    float vt[HS], g[HS], ze[HS];
#pragma unroll
    for (int i = 0; i < HS; i++) {
        const int s = sb + i;
        xs_sm[d * 17 + s] = Z[(size_t)(s0 + s) * DD + d];
        vs_sm[d * 17 + s] = V[(size_t)(s0 + s) * DD + d];
        ze[i] = Z[(size_t)(NB + s0 + s) * DD + d];
    }
    float mymin = 3.4e38f;   // meaningful for t < 16

    // matvec: acc[0..3] (f32x2) = sum_i W[i][d] * SRC[i][sb..sb+7]
    // 8-row blocks, one-block weight lookahead. Broadcast LDS.128 reads.
#define MATVEC(WB, SRC)                                                        \
    do {                                                                       \
        const float* Wcol = (WB) + d;                                          \
        const float* SRCP = (SRC) + sb;                                        \
        float wc[8], wn[8];                                                    \
        _Pragma("unroll") for (int u = 0; u < 8; u++) wc[u] = Wcol[u * DD];    \
        _Pragma("unroll") for (int k = 0; k < 4; k++) acc[k] = 0ull;           \
        _Pragma("unroll 1") for (int ii = 0; ii < DD; ii += 8) {               \
            if (ii + 8 < DD) {                                                 \
                _Pragma("unroll") for (int u = 0; u < 8; u++)                  \
                    wn[u] = Wcol[(ii + 8 + u) * DD];                           \
            }                                                                  \
            _Pragma("unroll") for (int u = 0; u < 8; u++) {                    \
                unsigned long long wp = pack2(wc[u], wc[u]);                   \
                const ulonglong2* xr =                                         \
                    (const ulonglong2*)(SRCP + (ii + u) * S);                  \
                ulonglong2 xv0 = xr[0];                                        \
                ulonglong2 xv1 = xr[1];                                        \
                acc[0] = fma2(wp, xv0.x, acc[0]);                              \
                acc[1] = fma2(wp, xv0.y, acc[1]);                              \
                acc[2] = fma2(wp, xv1.x, acc[2]);                              \
                acc[3] = fma2(wp, xv1.y, acc[3]);                              \
            }                                                                  \
            _Pragma("unroll") for (int u = 0; u < 8; u++) wc[u] = wn[u];       \
        }                                                                      \
    } while (0)

#define ACCEL()                                                                \
    do {                                                                       \
        __syncthreads(); /* xt published */                                    \
        unsigned long long acc[4];                                             \
        MATVEC(Wp1, xt_sm);                                                    \
        _Pragma("unroll") for (int k = 0; k < 4; k++) {                        \
            float2 p = unpack2(acc[k]);                                        \
            float h0 = tanhf(p.x + bp);                                        \
            float h1 = tanhf(p.y + bp);                                        \
            float2 sv;                                                         \
            sv.x = (1.0f - h0 * h0) * w2;                                      \
            sv.y = (1.0f - h1 * h1) * w2;                                      \
            *(float2*)(sv_sm + d * S + sb + 2 * k) = sv;                       \
        }                                                                      \
        __syncthreads(); /* sv published */                                    \
        MATVEC(WpT, sv_sm);                                                    \
        _Pragma("unroll") for (int k = 0; k < 4; k++) {                        \
            float2 p = unpack2(acc[k]);                                        \
            g[2 * k]     = p.x;                                                \
            g[2 * k + 1] = p.y;                                                \
        }                                                                      \
        _Pragma("unroll") for (int i = 0; i < HS; i++) {                       \
            float pg = g[i] * vt[i];                                           \
            float pv = vt[i] * vt[i];                                          \
            _Pragma("unroll") for (int off = 16; off > 0; off >>= 1) {         \
                pg += __shfl_xor_sync(0xffffffffu, pg, off);                   \
                pv += __shfl_xor_sync(0xffffffffu, pv, off);                   \
            }                                                                  \
            if (lane == 0) {                                                   \
                red_a[warp * S + sb + i] = pg;                                 \
                red_b[warp * S + sb + i] = pv;                                 \
            }                                                                  \
        }                                                                      \
        __syncthreads();                                                       \
        if (t < S) {                                                           \
            const int wb = (t < HS) ? 0 : 8;                                   \
            float sg = 0.f, sv2 = 0.f;                                         \
            _Pragma("unroll") for (int j = 0; j < 8; j++) {                    \
                sg  += red_a[(wb + j) * S + t];                                \
                sv2 += red_b[(wb + j) * S + t];                                \
            }                                                                  \
            bc_a[t] = sg;                                                      \
            bc_b[t] = sv2;                                                     \
        }                                                                      \
        __syncthreads();                                                       \
        _Pragma("unroll") for (int i = 0; i < HS; i++) {                       \
            const int s = sb + i;                                              \
            g[i] = 0.5f * bc_b[s] * g[i] - bc_a[s] * vt[i];                    \
        }                                                                      \
    } while (0)

    for (int step = 0; step < NSTEP; step++) {
        // ---- stage 1: xt = x, vt = v
#pragma unroll
        for (int i = 0; i < HS; i++) {
            const int s = sb + i;
            float xv = xs_sm[d * 17 + s];
            vt[i] = vs_sm[d * 17 + s];
            xt_sm[d * S + s] = xv;
        }
        ACCEL();
#pragma unroll
        for (int i = 0; i < HS; i++) {
            const int s = sb + i;
            xa_sm[d * 17 + s] = vt[i];
            va_sm[d * 17 + s] = g[i];
        }

        // ---- stage 2: xt = x + h/2 v, vt = v + h/2 a1
#pragma unroll
        for (int i = 0; i < HS; i++) {
            const int s = sb + i;
            float vv = vs_sm[d * 17 + s];
            xt_sm[d * S + s] = xs_sm[d * 17 + s] + 0.5f * hstep * vv;
            vt[i] = vv + 0.5f * hstep * g[i];
        }
        ACCEL();
#pragma unroll
        for (int i = 0; i < HS; i++) {
            const int s = sb + i;
            xa_sm[d * 17 + s] += 2.0f * vt[i];
            va_sm[d * 17 + s] += 2.0f * g[i];
        }

        // ---- stage 3: xt = x + h/2 k2x (k2x = current vt), vt = v + h/2 a2
#pragma unroll
        for (int i = 0; i < HS; i++) {
            const int s = sb + i;
            xt_sm[d * S + s] = xs_sm[d * 17 + s] + 0.5f * hstep * vt[i];
            float vv = vs_sm[d * 17 + s];
            vt[i] = vv + 0.5f * hstep * g[i];
        }
        ACCEL();
#pragma unroll
        for (int i = 0; i < HS; i++) {
            const int s = sb + i;
            xa_sm[d * 17 + s] += 2.0f * vt[i];
            va_sm[d * 17 + s] += 2.0f * g[i];
        }

        // ---- stage 4: xt = x + h k3x (k3x = current vt), vt = v + h a3
#pragma unroll
        for (int i = 0; i < HS; i++) {
            const int s = sb + i;
            xt_sm[d * S + s] = xs_sm[d * 17 + s] + hstep * vt[i];
            float vv = vs_sm[d * 17 + s];
            vt[i] = vv + hstep * g[i];
        }
        ACCEL();

        // ---- final update + distance to z_e
#pragma unroll
        for (int i = 0; i < HS; i++) {
            const int s = sb + i;
            float xacc = xa_sm[d * 17 + s] + vt[i];
            float vacc = va_sm[d * 17 + s] + g[i];
            float xn = xs_sm[d * 17 + s] + (hstep / 6.0f) * xacc;
            xs_sm[d * 17 + s] = xn;
            vs_sm[d * 17 + s] += (hstep / 6.0f) * vacc;
            float dd = xn - ze[i];
            float p = dd * dd;
#pragma unroll
            for (int off = 16; off > 0; off >>= 1)
                p += __shfl_xor_sync(0xffffffffu, p, off);
            if (lane == 0) red_a[warp * S + s] = p;
        }
        __syncthreads();
        if (t < S) {
            const int wb = (t < HS) ? 0 : 8;
            float tot = 0.f;
#pragma unroll
            for (int j = 0; j < 8; j++) tot += red_a[(wb + j) * S + t];
            mymin = fminf(mymin, tot);
        }
        __syncthreads();
    }

    if (t < S) mind[s0 + t] = mymin;
#undef ACCEL
#undef MATVEC
}

// ---------------------------------------------------------------------------
// Deterministic final reduction: out = mean(mind) * WEIGHT
// ---------------------------------------------------------------------------
__global__ void reduce_kernel(const float* __restrict__ mind, float* __restrict__ out) {
    __shared__ float sm[1024];
    const int t = threadIdx.x;
    float a = mind[t] + mind[t + 1024] + mind[t + 2048] + mind[t + 3072];
    sm[t] = a;
    __syncthreads();
    for (int off = 512; off > 0; off >>= 1) {
        if (t < off) sm[t] += sm[t + off];
        __syncthreads();
    }
    if (t == 0) out[0] = sm[0] * (1.0f / (float)NB);
}

// ---------------------------------------------------------------------------
// Launch — order chosen so the TRACE is launch index 5 (ncu -s 5 -c 1)
// ---------------------------------------------------------------------------
extern "C" void kernel_launch(void* const* d_in, const int* in_sizes, int n_in,
                              void* d_out, int out_size) {
    const float* x_start = (const float*)d_in[0];
    const float* x_end   = (const float*)d_in[1];
    const float* noise   = (const float*)d_in[2];
    const float* W1  = (const float*)d_in[3];
    const float* b1  = (const float*)d_in[4];
    const float* W2  = (const float*)d_in[5];
    const float* b2  = (const float*)d_in[6];
    const float* Ww1 = (const float*)d_in[7];
    const float* bw1 = (const float*)d_in[8];
    const float* Ww2 = (const float*)d_in[9];
    const float* bw2 = (const float*)d_in[10];
    const float* Wp1 = (const float*)d_in[11];
    const float* bp1 = (const float*)d_in[12];
    const float* wp2 = (const float*)d_in[13];

    float *Hb, *Zb, *HWb, *Vb, *WpT, *Md;
    cudaGetSymbolAddress((void**)&Hb,  g_H);
    cudaGetSymbolAddress((void**)&Zb,  g_Z);
    cudaGetSymbolAddress((void**)&HWb, g_HW);
    cudaGetSymbolAddress((void**)&Vb,  g_V);
    cudaGetSymbolAddress((void**)&WpT, g_WpT);
    cudaGetSymbolAddress((void**)&Md,  g_mind);

    cudaFuncSetAttribute(trace_kernel,
                         cudaFuncAttributeMaxDynamicSharedMemorySize,
                         TR_SMEM_BYTES);

    // 0: Encoder layer 1 (start+end in one launch via gridDim.z)
    sgemm_kernel<1><<<dim3(HH / 128, NB / 128, 2), 256>>>(
        x_start, x_end, W1, b1, Hb, NB, HH, DIN);
    // 1: Encoder layer 2: Z = H @ W2 + b2 (both halves)
    sgemm_kernel<0><<<dim3(DD / 128, 2 * NB / 128), 256>>>(
        Hb, Hb, W2, b2, Zb, 2 * NB, DD, HH);
    // 2: wind hidden
    sgemm_kernel<1><<<dim3(DD / 128, NB / 128), 256>>>(
        Zb, Zb, Ww1, bw1, HWb, NB, DD, DD);
    // 3: wind output
    sgemm_kernel<0><<<dim3(DD / 128, NB / 128), 256>>>(
        HWb, HWb, Ww2, bw2, Vb, NB, DD, DD);
    // 4: fused Wp1-transpose + degenerate-wind fallback
    prep_kernel<<<DD + NB, DD>>>(Wp1, WpT, Vb, noise);
    // 5: RK4 geodesic trace (ncu capture target)
    trace_kernel<<<NB / S, TPB, TR_SMEM_BYTES>>>(Zb, Vb, Wp1, WpT, bp1, wp2, Md);
    // 6: mean
    reduce_kernel<<<1, 1024>>>(Md, (float*)d_out);
}

// round 11
// speedup vs baseline: 1.1538x; 1.1538x over previous
#include <cuda_runtime.h>
#include <cuda_bf16.h>
#include <cstdint>

// ---------------------------------------------------------------------------
// Problem constants
// ---------------------------------------------------------------------------
#define NB    4096
#define DIN   2048
#define HH    1024
#define DD    256
#define NSTEP 15
#define S     16

// ---------------------------------------------------------------------------
// Scratch (device globals; no allocation allowed)
// ---------------------------------------------------------------------------
__device__ float g_H   [2 * NB * HH];
__device__ float g_Z   [2 * NB * DD];
__device__ float g_HW  [NB * DD];
__device__ float g_V   [NB * DD];
__device__ float g_WpT [DD * DD];
__device__ float g_mind[NB];
__device__ __nv_bfloat16 g_Xhi [2 * NB * DIN];   // merged start|end, bf16 hi
__device__ __nv_bfloat16 g_Xlo [2 * NB * DIN];   // residual lo
__device__ __nv_bfloat16 g_W1Thi[HH * DIN];      // W1^T [N=1024][K=2048] hi
__device__ __nv_bfloat16 g_W1Tlo[HH * DIN];      // lo

// ---------------------------------------------------------------------------
// Packed fp32x2 helpers (FFMA2)
// ---------------------------------------------------------------------------
__device__ __forceinline__ unsigned long long pack2(float x, float y) {
    unsigned long long r;
    asm("mov.b64 %0, {%1, %2};" : "=l"(r) : "f"(x), "f"(y));
    return r;
}
__device__ __forceinline__ float2 unpack2(unsigned long long v) {
    float2 r;
    asm("mov.b64 {%0, %1}, %2;" : "=f"(r.x), "=f"(r.y) : "l"(v));
    return r;
}
__device__ __forceinline__ unsigned long long fma2(unsigned long long a,
                                                   unsigned long long b,
                                                   unsigned long long c) {
    unsigned long long d;
    asm("fma.rn.f32x2 %0, %1, %2, %3;" : "=l"(d) : "l"(a), "l"(b), "l"(c));
    return d;
}

// ---------------------------------------------------------------------------
// Warp-level bf16 MMA (sm_80-baseline PTX — compiles on compute_103)
// D(m16n8, f32) += A(m16k16, bf16 row) * B(n8k16, bf16 col)
// ---------------------------------------------------------------------------
__device__ __forceinline__ void mma_bf16(float* d, const uint32_t* a,
                                         const uint32_t* b) {
    asm volatile(
        "mma.sync.aligned.m16n8k16.row.col.f32.bf16.bf16.f32 "
        "{%0,%1,%2,%3}, {%4,%5,%6,%7}, {%8,%9}, {%0,%1,%2,%3};"
        : "+f"(d[0]), "+f"(d[1]), "+f"(d[2]), "+f"(d[3])
        : "r"(a[0]), "r"(a[1]), "r"(a[2]), "r"(a[3]), "r"(b[0]), "r"(b[1]));
}

// ---------------------------------------------------------------------------
// Conversions
// ---------------------------------------------------------------------------
__global__ void convX_kernel(const float* __restrict__ xs, const float* __restrict__ xe,
                             __nv_bfloat16* __restrict__ hi, __nv_bfloat16* __restrict__ lo) {
    const size_t i4 = ((size_t)blockIdx.x * blockDim.x + threadIdx.x) * 4;
    const size_t half = (size_t)NB * DIN;
    const float* src = (i4 < half) ? xs + i4 : xe + (i4 - half);
    float4 v = *(const float4*)src;
    float vv[4] = {v.x, v.y, v.z, v.w};
    __nv_bfloat16 h[4], l[4];
#pragma unroll
    for (int j = 0; j < 4; j++) {
        h[j] = __float2bfloat16(vv[j]);
        l[j] = __float2bfloat16(vv[j] - __bfloat162float(h[j]));
    }
    *(uint2*)(hi + i4) = *(uint2*)h;
    *(uint2*)(lo + i4) = *(uint2*)l;
}

__global__ void convW_kernel(const float* __restrict__ W1,
                             __nv_bfloat16* __restrict__ hi, __nv_bfloat16* __restrict__ lo) {
    __shared__ float tile[32][33];
    const int n0 = blockIdx.x * 32, k0 = blockIdx.y * 32;
    const int tx = threadIdx.x, ty = threadIdx.y;
    tile[ty][tx] = W1[(size_t)(k0 + ty) * HH + n0 + tx];
    __syncthreads();
    float v = tile[tx][ty];                      // = W1[k0+tx][n0+ty]
    __nv_bfloat16 h = __float2bfloat16(v);
    __nv_bfloat16 l = __float2bfloat16(v - __bfloat162float(h));
    hi[(size_t)(n0 + ty) * DIN + k0 + tx] = h;
    lo[(size_t)(n0 + ty) * DIN + k0 + tx] = l;
}

// ---------------------------------------------------------------------------
// enc1 via HMMA: H = tanh(X @ W1 + b1), bf16x3 split.
// CTA tile 128(M) x 128(N), 8 warps in 4x2 (warp tile 32x64).
// K chunks of 32. smem stride 40 bf16 per row (conflict-free).
// ---------------------------------------------------------------------------
#define TSTR 40   // smem row stride in bf16

__device__ __forceinline__ void enc_load_tile(__nv_bfloat16* s,
                                              const __nv_bfloat16* __restrict__ g,
                                              int row0, int k0, int tid) {
#pragma unroll
    for (int i = 0; i < 2; i++) {
        const int cid = tid + i * 256;       // 512 chunks of 16B
        const int r = cid >> 2;
        const int c = (cid & 3) * 8;
        uint4 v = *(const uint4*)(g + (size_t)(row0 + r) * DIN + k0 + c);
        *(uint4*)(s + r * TSTR + c) = v;
    }
}

__global__ __launch_bounds__(256, 2)
void enc1_mma_kernel(const __nv_bfloat16* __restrict__ Xhi,
                     const __nv_bfloat16* __restrict__ Xlo,
                     const __nv_bfloat16* __restrict__ Whi,
                     const __nv_bfloat16* __restrict__ Wlo,
                     const float* __restrict__ b1, float* __restrict__ H) {
    __shared__ __align__(16) __nv_bfloat16 Ah[128 * TSTR];
    __shared__ __align__(16) __nv_bfloat16 Al[128 * TSTR];
    __shared__ __align__(16) __nv_bfloat16 Bh[128 * TSTR];
    __shared__ __align__(16) __nv_bfloat16 Bl[128 * TSTR];

    const int tid  = threadIdx.x;
    const int wid  = tid >> 5;
    const int lane = tid & 31;
    const int n0   = blockIdx.x * 128;
    const int m0   = blockIdx.y * 128;
    const int wm   = (wid & 3) * 32;       // warp m offset in tile
    const int wn   = (wid >> 2) * 64;      // warp n offset in tile
    const int r    = lane >> 2;            // 0..7
    const int c2   = (lane & 3) * 2;       // 0,2,4,6

    float d[2][8][4];
#pragma unroll
    for (int mf = 0; mf < 2; mf++)
#pragma unroll
        for (int nf = 0; nf < 8; nf++)
#pragma unroll
            for (int j = 0; j < 4; j++) d[mf][nf][j] = 0.0f;

    for (int ch = 0; ch < DIN / 32; ch++) {
        const int k0 = ch * 32;
        __syncthreads();
        enc_load_tile(Ah, Xhi, m0, k0, tid);
        enc_load_tile(Al, Xlo, m0, k0, tid);
        enc_load_tile(Bh, Whi, n0, k0, tid);
        enc_load_tile(Bl, Wlo, n0, k0, tid);
        __syncthreads();

#pragma unroll
        for (int kk = 0; kk < 32; kk += 16) {
            uint32_t ah[2][4], al[2][4];
#pragma unroll
            for (int mf = 0; mf < 2; mf++) {
                const int mb = wm + mf * 16;
                ah[mf][0] = *(const uint32_t*)&Ah[(mb + r) * TSTR + kk + c2];
                ah[mf][1] = *(const uint32_t*)&Ah[(mb + r + 8) * TSTR + kk + c2];
                ah[mf][2] = *(const uint32_t*)&Ah[(mb + r) * TSTR + kk + c2 + 8];
                ah[mf][3] = *(const uint32_t*)&Ah[(mb + r + 8) * TSTR + kk + c2 + 8];
                al[mf][0] = *(const uint32_t*)&Al[(mb + r) * TSTR + kk + c2];
                al[mf][1] = *(const uint32_t*)&Al[(mb + r + 8) * TSTR + kk + c2];
                al[mf][2] = *(const uint32_t*)&Al[(mb + r) * TSTR + kk + c2 + 8];
                al[mf][3] = *(const uint32_t*)&Al[(mb + r + 8) * TSTR + kk + c2 + 8];
            }
#pragma unroll
            for (int nf = 0; nf < 8; nf++) {
                const int nb = wn + nf * 8 + r;
                uint32_t bh[2], bl[2];
                bh[0] = *(const uint32_t*)&Bh[nb * TSTR + kk + c2];
                bh[1] = *(const uint32_t*)&Bh[nb * TSTR + kk + c2 + 8];
                bl[0] = *(const uint32_t*)&Bl[nb * TSTR + kk + c2];
                bl[1] = *(const uint32_t*)&Bl[nb * TSTR + kk + c2 + 8];
#pragma unroll
                for (int mf = 0; mf < 2; mf++) {
                    mma_bf16(d[mf][nf], ah[mf], bh);
                    mma_bf16(d[mf][nf], ah[mf], bl);
                    mma_bf16(d[mf][nf], al[mf], bh);
                }
            }
        }
    }

    // epilogue: bias + tanh, float2 stores
#pragma unroll
    for (int mf = 0; mf < 2; mf++) {
        const int row = m0 + wm + mf * 16 + r;
#pragma unroll
        for (int nf = 0; nf < 8; nf++) {
            const int col = n0 + wn + nf * 8 + c2;
            const float bb0 = b1[col], bb1 = b1[col + 1];
            float2 p0, p1;
            p0.x = tanhf(d[mf][nf][0] + bb0);
            p0.y = tanhf(d[mf][nf][1] + bb1);
            p1.x = tanhf(d[mf][nf][2] + bb0);
            p1.y = tanhf(d[mf][nf][3] + bb1);
            *(float2*)&H[(size_t)row * HH + col] = p0;
            *(float2*)&H[(size_t)(row + 8) * HH + col] = p1;
        }
    }
}

// ---------------------------------------------------------------------------
// SGEMM (R4 exact)
// ---------------------------------------------------------------------------
#define ASTRIDE 132

template <int ACT>
__global__ __launch_bounds__(256)
void sgemm_kernel(const float* __restrict__ A, const float* __restrict__ Bm,
                  const float* __restrict__ bias, float* __restrict__ C,
                  int M, int N, int K) {
    __shared__ __align__(16) float As[2 * 16 * ASTRIDE];
    __shared__ __align__(16) float Bs[2 * 16 * 128];

    const int tid  = threadIdx.x;
    const int brow = blockIdx.y * 128;
    const int bcol = blockIdx.x * 128;
    const int ty   = tid >> 4;
    const int tx   = tid & 15;
    const int arow = tid >> 1;
    const int acol = (tid & 1) * 8;
    const int br0  = tid >> 5;
    const int bcl  = (tid & 31) * 4;

    const float* Aptr = A  + (size_t)(brow + arow) * K + acol;
    const float* Bptr = Bm + (size_t)br0 * N + bcol + bcl;

    unsigned long long c2[8][4];
#pragma unroll
    for (int m = 0; m < 8; m++)
#pragma unroll
        for (int j = 0; j < 4; j++) c2[m][j] = 0ull;

    float4 a_rg0, a_rg1, b_rg0, b_rg1;
    a_rg0 = *(const float4*)(Aptr + 0);
    a_rg1 = *(const float4*)(Aptr + 4);
    b_rg0 = *(const float4*)(Bptr);
    b_rg1 = *(const float4*)(Bptr + (size_t)8 * N);
    {
        float am[8] = {a_rg0.x, a_rg0.y, a_rg0.z, a_rg0.w,
                       a_rg1.x, a_rg1.y, a_rg1.z, a_rg1.w};
#pragma unroll
        for (int c = 0; c < 8; c++) As[(acol + c) * ASTRIDE + arow] = am[c];
        *(float4*)&Bs[br0 * 128 + bcl]       = b_rg0;
        *(float4*)&Bs[(br0 + 8) * 128 + bcl] = b_rg1;
    }
    __syncthreads();

    int buf = 0;
    const int nblk = K / 16;
    for (int kb = 0; kb < nblk; kb++) {
        const bool has_next = (kb + 1 < nblk);
        if (has_next) {
            const int k0 = (kb + 1) * 16;
            a_rg0 = *(const float4*)(Aptr + k0);
            a_rg1 = *(const float4*)(Aptr + k0 + 4);
            b_rg0 = *(const float4*)(Bptr + (size_t)k0 * N);
            b_rg1 = *(const float4*)(Bptr + (size_t)(k0 + 8) * N);
        }
        const float* Asb = As + buf * 16 * ASTRIDE;
        const float* Bsb = Bs + buf * 16 * 128;
#pragma unroll
        for (int kk = 0; kk < 16; kk++) {
            float4 a0 = *(const float4*)&Asb[kk * ASTRIDE + ty * 8];
            float4 a1 = *(const float4*)&Asb[kk * ASTRIDE + ty * 8 + 4];
            const unsigned long long* brow2 =
                (const unsigned long long*)&Bsb[kk * 128 + tx * 8];
            unsigned long long b2[4];
#pragma unroll
            for (int j = 0; j < 4; j++) b2[j] = brow2[j];
            float am[8] = {a0.x, a0.y, a0.z, a0.w, a1.x, a1.y, a1.z, a1.w};
#pragma unroll
            for (int m = 0; m < 8; m++) {
                unsigned long long aa = pack2(am[m], am[m]);
#pragma unroll
                for (int j = 0; j < 4; j++) c2[m][j] = fma2(aa, b2[j], c2[m][j]);
            }
        }
        if (has_next) {
            float* Asn = As + (buf ^ 1) * 16 * ASTRIDE;
            float* Bsn = Bs + (buf ^ 1) * 16 * 128;
            float am[8] = {a_rg0.x, a_rg0.y, a_rg0.z, a_rg0.w,
                           a_rg1.x, a_rg1.y, a_rg1.z, a_rg1.w};
#pragma unroll
            for (int c = 0; c < 8; c++) Asn[(acol + c) * ASTRIDE + arow] = am[c];
            *(float4*)&Bsn[br0 * 128 + bcl]       = b_rg0;
            *(float4*)&Bsn[(br0 + 8) * 128 + bcl] = b_rg1;
            __syncthreads();
            buf ^= 1;
        }
    }
#pragma unroll
    for (int m = 0; m < 8; m++) {
        const int row = brow + ty * 8 + m;
        float* crow = C + (size_t)row * N + bcol + tx * 8;
#pragma unroll
        for (int j = 0; j < 4; j++) {
            float2 p = unpack2(c2[m][j]);
            const int n = bcol + tx * 8 + 2 * j;
            p.x += bias[n];
            p.y += bias[n + 1];
            if (ACT) { p.x = tanhf(p.x); p.y = tanhf(p.y); }
            *(float2*)&crow[2 * j] = p;
        }
    }
}

// ---------------------------------------------------------------------------
__global__ void transpose256(const float* __restrict__ in, float* __restrict__ out) {
    int i = blockIdx.x, j = threadIdx.x;
    out[j * DD + i] = in[i * DD + j];
}

__global__ void fallback_kernel(float* __restrict__ V, const float* __restrict__ noise) {
    __shared__ float rw[8], rn[8];
    const int s = blockIdx.x, t = threadIdx.x;
    const int lane = t & 31, warp = t >> 5;
    float w = V[s * DD + t];
    float n = noise[s * DD + t];
    float pw = w * w, pn = n * n;
#pragma unroll
    for (int off = 16; off > 0; off >>= 1) {
        pw += __shfl_xor_sync(0xffffffffu, pw, off);
        pn += __shfl_xor_sync(0xffffffffu, pn, off);
    }
    if (lane == 0) { rw[warp] = pw; rn[warp] = pn; }
    __syncthreads();
    float sw = 0.f, sn = 0.f;
#pragma unroll
    for (int i = 0; i < 8; i++) { sw += rw[i]; sn += rn[i]; }
    float wn = sqrtf(sw + 1e-24f);
    if (wn < 1e-5f) {
        float nn = sqrtf(sn + 1e-24f);
        V[s * DD + t] = w + n / (nn + 1e-12f) * 1e-4f;
    }
}

// ---------------------------------------------------------------------------
// Trace kernel (R4 exact)
// ---------------------------------------------------------------------------
__global__ __launch_bounds__(256, 2)
void trace_kernel(const float* __restrict__ Z, const float* __restrict__ V,
                  const float* __restrict__ Wp1, const float* __restrict__ WpT,
                  const float* __restrict__ bp1, const float* __restrict__ wp2,
                  float* __restrict__ mind) {
    __shared__ __align__(16) float xt_sm[DD * S];
    __shared__ __align__(16) float sv_sm[DD * S];
    __shared__ float red_a[8 * S];
    __shared__ float red_b[8 * S];
    __shared__ float bc_a[S];
    __shared__ float bc_b[S];

    const int t    = threadIdx.x;
    const int lane = t & 31;
    const int warp = t >> 5;
    const int s0   = blockIdx.x * S;
    const float hstep = 1.0f / 15.0f;
    const float bp = bp1[t];
    const float w2 = wp2[t];

    float x[S], v[S], vt[S], g[S], xacc[S], vacc[S];
#pragma unroll
    for (int s = 0; s < S; s++) {
        x[s] = Z[(size_t)(s0 + s) * DD + t];
        v[s] = V[(size_t)(s0 + s) * DD + t];
    }
    float mymin = 3.4e38f;

#define MATVEC(WBASE, SRC, ACC2)                                               \
    do {                                                                       \
        const float* Wcol = (WBASE) + t;                                       \
        float wc[8], wn[8];                                                    \
        _Pragma("unroll") for (int u = 0; u < 8; u++) wc[u] = Wcol[u * DD];    \
        _Pragma("unroll") for (int k = 0; k < S / 2; k++) ACC2[k] = 0ull;      \
        _Pragma("unroll 1") for (int ii = 0; ii < DD; ii += 8) {               \
            if (ii + 8 < DD) {                                                 \
                _Pragma("unroll") for (int u = 0; u < 8; u++)                  \
                    wn[u] = Wcol[(ii + 8 + u) * DD];                           \
            }                                                                  \
            _Pragma("unroll") for (int u = 0; u < 8; u++) {                    \
                unsigned long long wp = pack2(wc[u], wc[u]);                   \
                const ulonglong2* xr = (const ulonglong2*)((SRC) + (ii + u) * S); \
                _Pragma("unroll") for (int k = 0; k < S / 4; k++) {            \
                    ulonglong2 xv = xr[k];                                     \
                    ACC2[2 * k]     = fma2(wp, xv.x, ACC2[2 * k]);             \
                    ACC2[2 * k + 1] = fma2(wp, xv.y, ACC2[2 * k + 1]);         \
                }                                                              \
            }                                                                  \
            _Pragma("unroll") for (int u = 0; u < 8; u++) wc[u] = wn[u];       \
        }                                                                      \
    } while (0)

#define ACCEL()                                                                \
    do {                                                                       \
        __syncthreads();                                                       \
        {                                                                      \
            unsigned long long acc2[S / 2];                                    \
            MATVEC(Wp1, xt_sm, acc2);                                          \
            _Pragma("unroll") for (int k = 0; k < S / 2; k++) {                \
                float2 p = unpack2(acc2[k]);                                   \
                float h0 = tanhf(p.x + bp);                                    \
                float h1 = tanhf(p.y + bp);                                    \
                float2 ssv;                                                    \
                ssv.x = (1.0f - h0 * h0) * w2;                                 \
                ssv.y = (1.0f - h1 * h1) * w2;                                 \
                *(float2*)(sv_sm + t * S + 2 * k) = ssv;                       \
            }                                                                  \
        }                                                                      \
        __syncthreads();                                                       \
        {                                                                      \
            unsigned long long acc2[S / 2];                                    \
            MATVEC(WpT, sv_sm, acc2);                                          \
            _Pragma("unroll") for (int k = 0; k < S / 2; k++) {                \
                float2 p = unpack2(acc2[k]);                                   \
                g[2 * k]     = p.x;                                            \
                g[2 * k + 1] = p.y;                                            \
            }                                                                  \
        }                                                                      \
        _Pragma("unroll") for (int s = 0; s < S; s++) {                        \
            float pg = g[s] * vt[s];                                           \
            float pv = vt[s] * vt[s];                                          \
            _Pragma("unroll") for (int off = 16; off > 0; off >>= 1) {         \
                pg += __shfl_xor_sync(0xffffffffu, pg, off);                   \
                pv += __shfl_xor_sync(0xffffffffu, pv, off);                   \
            }                                                                  \
            if (lane == 0) {                                                   \
                red_a[warp * S + s] = pg;                                      \
                red_b[warp * S + s] = pv;                                      \
            }                                                                  \
        }                                                                      \
        __syncthreads();                                                       \
        if (t < S) {                                                           \
            float sg = 0.f, sv2 = 0.f;                                         \
            _Pragma("unroll") for (int w8 = 0; w8 < 8; w8++) {                 \
                sg += red_a[w8 * S + t];                                       \
                sv2 += red_b[w8 * S + t];                                      \
            }                                                                  \
            bc_a[t] = sg;                                                      \
            bc_b[t] = sv2;                                                     \
        }                                                                      \
        __syncthreads();                                                       \
        _Pragma("unroll") for (int s = 0; s < S; s++) {                        \
            g[s] = 0.5f * bc_b[s] * g[s] - bc_a[s] * vt[s];                    \
        }                                                                      \
    } while (0)

    for (int step = 0; step < NSTEP; step++) {
#pragma unroll
        for (int s = 0; s < S; s++) {
            xt_sm[t * S + s] = x[s];
            vt[s] = v[s];
        }
        ACCEL();
#pragma unroll
        for (int s = 0; s < S; s++) { xacc[s] = v[s]; vacc[s] = g[s]; }

#pragma unroll
        for (int s = 0; s < S; s++) {
            xt_sm[t * S + s] = x[s] + 0.5f * hstep * v[s];
            vt[s] = v[s] + 0.5f * hstep * g[s];
        }
        ACCEL();
#pragma unroll
        for (int s = 0; s < S; s++) { xacc[s] += 2.0f * vt[s]; vacc[s] += 2.0f * g[s]; }

#pragma unroll
        for (int s = 0; s < S; s++) {
            float k2x = vt[s];
            xt_sm[t * S + s] = x[s] + 0.5f * hstep * k2x;
            vt[s] = v[s] + 0.5f * hstep * g[s];
        }
        ACCEL();
#pragma unroll
        for (int s = 0; s < S; s++) { xacc[s] += 2.0f * vt[s]; vacc[s] += 2.0f * g[s]; }

#pragma unroll
        for (int s = 0; s < S; s++) {
            float k3x = vt[s];
            xt_sm[t * S + s] = x[s] + hstep * k3x;
            vt[s] = v[s] + hstep * g[s];
        }
        ACCEL();
#pragma unroll
        for (int s = 0; s < S; s++) {
            xacc[s] += vt[s];
            vacc[s] += g[s];
            x[s] += (hstep / 6.0f) * xacc[s];
            v[s] += (hstep / 6.0f) * vacc[s];
        }

#pragma unroll
        for (int s = 0; s < S; s++) {
            float dd = x[s] - Z[(size_t)(NB + s0 + s) * DD + t];
            float p = dd * dd;
#pragma unroll
            for (int off = 16; off > 0; off >>= 1)
                p += __shfl_xor_sync(0xffffffffu, p, off);
            if (lane == 0) red_a[warp * S + s] = p;
        }
        __syncthreads();
        if (t < S) {
            float tot = 0.f;
#pragma unroll
            for (int w8 = 0; w8 < 8; w8++) tot += red_a[w8 * S + t];
            mymin = fminf(mymin, tot);
        }
        __syncthreads();
    }

    if (t < S) mind[s0 + t] = mymin;
#undef ACCEL
#undef MATVEC
}

// ---------------------------------------------------------------------------
__global__ void reduce_kernel(const float* __restrict__ mind, float* __restrict__ out) {
    __shared__ float sm[1024];
    const int t = threadIdx.x;
    float a = mind[t] + mind[t + 1024] + mind[t + 2048] + mind[t + 3072];
    sm[t] = a;
    __syncthreads();
    for (int off = 512; off > 0; off >>= 1) {
        if (t < off) sm[t] += sm[t + off];
        __syncthreads();
    }
    if (t == 0) out[0] = sm[0] * (1.0f / (float)NB);
}

// ---------------------------------------------------------------------------
// Launch
// ---------------------------------------------------------------------------
extern "C" void kernel_launch(void* const* d_in, const int* in_sizes, int n_in,
                              void* d_out, int out_size) {
    const float* x_start = (const float*)d_in[0];
    const float* x_end   = (const float*)d_in[1];
    const float* noise   = (const float*)d_in[2];
    const float* W1  = (const float*)d_in[3];
    const float* b1  = (const float*)d_in[4];
    const float* W2  = (const float*)d_in[5];
    const float* b2  = (const float*)d_in[6];
    const float* Ww1 = (const float*)d_in[7];
    const float* bw1 = (const float*)d_in[8];
    const float* Ww2 = (const float*)d_in[9];
    const float* bw2 = (const float*)d_in[10];
    const float* Wp1 = (const float*)d_in[11];
    const float* bp1 = (const float*)d_in[12];
    const float* wp2 = (const float*)d_in[13];

    float *Hb, *Zb, *HWb, *Vb, *WpT, *Md;
    cudaGetSymbolAddress((void**)&Hb,  g_H);
    cudaGetSymbolAddress((void**)&Zb,  g_Z);
    cudaGetSymbolAddress((void**)&HWb, g_HW);
    cudaGetSymbolAddress((void**)&Vb,  g_V);
    cudaGetSymbolAddress((void**)&WpT, g_WpT);
    cudaGetSymbolAddress((void**)&Md,  g_mind);
    __nv_bfloat16 *Xhi, *Xlo, *Whi, *Wlo;
    cudaGetSymbolAddress((void**)&Xhi, g_Xhi);
    cudaGetSymbolAddress((void**)&Xlo, g_Xlo);
    cudaGetSymbolAddress((void**)&Whi, g_W1Thi);
    cudaGetSymbolAddress((void**)&Wlo, g_W1Tlo);

    // conversions for enc1
    convX_kernel<<<(2 * NB * DIN / 4) / 256, 256>>>(x_start, x_end, Xhi, Xlo);
    convW_kernel<<<dim3(HH / 32, DIN / 32), dim3(32, 32)>>>(W1, Whi, Wlo);
    // enc1 on tensor cores (HMMA bf16x3)
    enc1_mma_kernel<<<dim3(HH / 128, 2 * NB / 128), 256>>>(
        Xhi, Xlo, Whi, Wlo, b1, Hb);
    // enc2: Z = H @ W2 + b2
    sgemm_kernel<0><<<dim3(DD / 128, 2 * NB / 128), 256>>>(Hb, W2, b2, Zb, 2 * NB, DD, HH);
    // wind field
    sgemm_kernel<1><<<dim3(DD / 128, NB / 128), 256>>>(Zb,  Ww1, bw1, HWb, NB, DD, DD);
    sgemm_kernel<0><<<dim3(DD / 128, NB / 128), 256>>>(HWb, Ww2, bw2, Vb,  NB, DD, DD);
    // prep
    transpose256<<<DD, DD>>>(Wp1, WpT);
    fallback_kernel<<<NB, DD>>>(Vb, noise);
    // trace + mean
    trace_kernel<<<NB / S, DD>>>(Zb, Vb, Wp1, WpT, bp1, wp2, Md);
    reduce_kernel<<<1, 1024>>>(Md, (float*)d_out);
}

// round 13
// speedup vs baseline: 2.0967x; 1.8172x over previous
#include <cuda_runtime.h>
#include <cuda_bf16.h>
#include <cstdint>

// ---------------------------------------------------------------------------
// Problem constants
// ---------------------------------------------------------------------------
#define NB    4096
#define DIN   2048
#define HH    1024
#define DD    256
#define NSTEP 15
#define SC    32     // samples per trace CTA

// ---------------------------------------------------------------------------
// Scratch (device globals; no allocation allowed)
// ---------------------------------------------------------------------------
__device__ float g_H   [2 * NB * HH];
__device__ float g_Z   [2 * NB * DD];
__device__ float g_HW  [NB * DD];
__device__ float g_V   [NB * DD];
__device__ float g_mind[NB];
__device__ __nv_bfloat16 g_Xhi [2 * NB * DIN];
__device__ __nv_bfloat16 g_Xlo [2 * NB * DIN];
__device__ __nv_bfloat16 g_W1Thi[HH * DIN];
__device__ __nv_bfloat16 g_W1Tlo[HH * DIN];
// trace weights, bf16 hi/lo: W  = Wp1[n][k]      (matvec2 B operand)
//                            WT = Wp1^T[n][k]    (matvec1 B operand)
__device__ __nv_bfloat16 g_Wbhi [DD * DD];
__device__ __nv_bfloat16 g_Wblo [DD * DD];
__device__ __nv_bfloat16 g_WTbhi[DD * DD];
__device__ __nv_bfloat16 g_WTblo[DD * DD];

// ---------------------------------------------------------------------------
// Packed fp32x2 helpers (FFMA2)
// ---------------------------------------------------------------------------
__device__ __forceinline__ unsigned long long pack2(float x, float y) {
    unsigned long long r;
    asm("mov.b64 %0, {%1, %2};" : "=l"(r) : "f"(x), "f"(y));
    return r;
}
__device__ __forceinline__ float2 unpack2(unsigned long long v) {
    float2 r;
    asm("mov.b64 {%0, %1}, %2;" : "=f"(r.x), "=f"(r.y) : "l"(v));
    return r;
}
__device__ __forceinline__ unsigned long long fma2(unsigned long long a,
                                                   unsigned long long b,
                                                   unsigned long long c) {
    unsigned long long d;
    asm("fma.rn.f32x2 %0, %1, %2, %3;" : "=l"(d) : "l"(a), "l"(b), "l"(c));
    return d;
}

// ---------------------------------------------------------------------------
// Warp-level bf16 MMA
// ---------------------------------------------------------------------------
__device__ __forceinline__ void mma_bf16(float* d, const uint32_t* a,
                                         const uint32_t* b) {
    asm volatile(
        "mma.sync.aligned.m16n8k16.row.col.f32.bf16.bf16.f32 "
        "{%0,%1,%2,%3}, {%4,%5,%6,%7}, {%8,%9}, {%0,%1,%2,%3};"
        : "+f"(d[0]), "+f"(d[1]), "+f"(d[2]), "+f"(d[3])
        : "r"(a[0]), "r"(a[1]), "r"(a[2]), "r"(a[3]), "r"(b[0]), "r"(b[1]));
}

// ---------------------------------------------------------------------------
// Conversions for enc1
// ---------------------------------------------------------------------------
__global__ void convX_kernel(const float* __restrict__ xs, const float* __restrict__ xe,
                             __nv_bfloat16* __restrict__ hi, __nv_bfloat16* __restrict__ lo) {
    const size_t i4 = ((size_t)blockIdx.x * blockDim.x + threadIdx.x) * 4;
    const size_t half = (size_t)NB * DIN;
    const float* src = (i4 < half) ? xs + i4 : xe + (i4 - half);
    float4 v = *(const float4*)src;
    float vv[4] = {v.x, v.y, v.z, v.w};
    __nv_bfloat16 h[4], l[4];
#pragma unroll
    for (int j = 0; j < 4; j++) {
        h[j] = __float2bfloat16(vv[j]);
        l[j] = __float2bfloat16(vv[j] - __bfloat162float(h[j]));
    }
    *(uint2*)(hi + i4) = *(uint2*)h;
    *(uint2*)(lo + i4) = *(uint2*)l;
}

__global__ void convW_kernel(const float* __restrict__ W1,
                             __nv_bfloat16* __restrict__ hi, __nv_bfloat16* __restrict__ lo) {
    __shared__ float tile[32][33];
    const int n0 = blockIdx.x * 32, k0 = blockIdx.y * 32;
    const int tx = threadIdx.x, ty = threadIdx.y;
    tile[ty][tx] = W1[(size_t)(k0 + ty) * HH + n0 + tx];
    __syncthreads();
    float v = tile[tx][ty];
    __nv_bfloat16 h = __float2bfloat16(v);
    __nv_bfloat16 l = __float2bfloat16(v - __bfloat162float(h));
    hi[(size_t)(n0 + ty) * DIN + k0 + tx] = h;
    lo[(size_t)(n0 + ty) * DIN + k0 + tx] = l;
}

// Wp1 [256][256] -> W hi/lo ([n][k] natural) and WT hi/lo (transposed)
__global__ void prepW_kernel(const float* __restrict__ Wp1,
                             __nv_bfloat16* __restrict__ Whi, __nv_bfloat16* __restrict__ Wlo,
                             __nv_bfloat16* __restrict__ WThi, __nv_bfloat16* __restrict__ WTlo) {
    const int i = blockIdx.x, j = threadIdx.x;
    float w = Wp1[i * DD + j];
    __nv_bfloat16 h = __float2bfloat16(w);
    Whi[i * DD + j] = h;
    Wlo[i * DD + j] = __float2bfloat16(w - __bfloat162float(h));
    float wt = Wp1[j * DD + i];
    __nv_bfloat16 ht = __float2bfloat16(wt);
    WThi[i * DD + j] = ht;
    WTlo[i * DD + j] = __float2bfloat16(wt - __bfloat162float(ht));
}

// ---------------------------------------------------------------------------
// enc1 via HMMA (R11 exact)
// ---------------------------------------------------------------------------
#define TSTR 40

__device__ __forceinline__ void enc_load_tile(__nv_bfloat16* s,
                                              const __nv_bfloat16* __restrict__ g,
                                              int row0, int k0, int tid) {
#pragma unroll
    for (int i = 0; i < 2; i++) {
        const int cid = tid + i * 256;
        const int r = cid >> 2;
        const int c = (cid & 3) * 8;
        uint4 v = *(const uint4*)(g + (size_t)(row0 + r) * DIN + k0 + c);
        *(uint4*)(s + r * TSTR + c) = v;
    }
}

__global__ __launch_bounds__(256, 2)
void enc1_mma_kernel(const __nv_bfloat16* __restrict__ Xhi,
                     const __nv_bfloat16* __restrict__ Xlo,
                     const __nv_bfloat16* __restrict__ Whi,
                     const __nv_bfloat16* __restrict__ Wlo,
                     const float* __restrict__ b1, float* __restrict__ H) {
    __shared__ __align__(16) __nv_bfloat16 Ah[128 * TSTR];
    __shared__ __align__(16) __nv_bfloat16 Al[128 * TSTR];
    __shared__ __align__(16) __nv_bfloat16 Bh[128 * TSTR];
    __shared__ __align__(16) __nv_bfloat16 Bl[128 * TSTR];

    const int tid  = threadIdx.x;
    const int wid  = tid >> 5;
    const int lane = tid & 31;
    const int n0   = blockIdx.x * 128;
    const int m0   = blockIdx.y * 128;
    const int wm   = (wid & 3) * 32;
    const int wn   = (wid >> 2) * 64;
    const int r    = lane >> 2;
    const int c2   = (lane & 3) * 2;

    float d[2][8][4];
#pragma unroll
    for (int mf = 0; mf < 2; mf++)
#pragma unroll
        for (int nf = 0; nf < 8; nf++)
#pragma unroll
            for (int j = 0; j < 4; j++) d[mf][nf][j] = 0.0f;

    for (int ch = 0; ch < DIN / 32; ch++) {
        const int k0 = ch * 32;
        __syncthreads();
        enc_load_tile(Ah, Xhi, m0, k0, tid);
        enc_load_tile(Al, Xlo, m0, k0, tid);
        enc_load_tile(Bh, Whi, n0, k0, tid);
        enc_load_tile(Bl, Wlo, n0, k0, tid);
        __syncthreads();

#pragma unroll
        for (int kk = 0; kk < 32; kk += 16) {
            uint32_t ah[2][4], al[2][4];
#pragma unroll
            for (int mf = 0; mf < 2; mf++) {
                const int mb = wm + mf * 16;
                ah[mf][0] = *(const uint32_t*)&Ah[(mb + r) * TSTR + kk + c2];
                ah[mf][1] = *(const uint32_t*)&Ah[(mb + r + 8) * TSTR + kk + c2];
                ah[mf][2] = *(const uint32_t*)&Ah[(mb + r) * TSTR + kk + c2 + 8];
                ah[mf][3] = *(const uint32_t*)&Ah[(mb + r + 8) * TSTR + kk + c2 + 8];
                al[mf][0] = *(const uint32_t*)&Al[(mb + r) * TSTR + kk + c2];
                al[mf][1] = *(const uint32_t*)&Al[(mb + r + 8) * TSTR + kk + c2];
                al[mf][2] = *(const uint32_t*)&Al[(mb + r) * TSTR + kk + c2 + 8];
                al[mf][3] = *(const uint32_t*)&Al[(mb + r + 8) * TSTR + kk + c2 + 8];
            }
#pragma unroll
            for (int nf = 0; nf < 8; nf++) {
                const int nb = wn + nf * 8 + r;
                uint32_t bh[2], bl[2];
                bh[0] = *(const uint32_t*)&Bh[nb * TSTR + kk + c2];
                bh[1] = *(const uint32_t*)&Bh[nb * TSTR + kk + c2 + 8];
                bl[0] = *(const uint32_t*)&Bl[nb * TSTR + kk + c2];
                bl[1] = *(const uint32_t*)&Bl[nb * TSTR + kk + c2 + 8];
#pragma unroll
                for (int mf = 0; mf < 2; mf++) {
                    mma_bf16(d[mf][nf], ah[mf], bh);
                    mma_bf16(d[mf][nf], ah[mf], bl);
                    mma_bf16(d[mf][nf], al[mf], bh);
                }
            }
        }
    }

#pragma unroll
    for (int mf = 0; mf < 2; mf++) {
        const int row = m0 + wm + mf * 16 + r;
#pragma unroll
        for (int nf = 0; nf < 8; nf++) {
            const int col = n0 + wn + nf * 8 + c2;
            const float bb0 = b1[col], bb1 = b1[col + 1];
            float2 p0, p1;
            p0.x = tanhf(d[mf][nf][0] + bb0);
            p0.y = tanhf(d[mf][nf][1] + bb1);
            p1.x = tanhf(d[mf][nf][2] + bb0);
            p1.y = tanhf(d[mf][nf][3] + bb1);
            *(float2*)&H[(size_t)row * HH + col] = p0;
            *(float2*)&H[(size_t)(row + 8) * HH + col] = p1;
        }
    }
}

// ---------------------------------------------------------------------------
// SGEMM (R4 exact) for enc2 / winds
// ---------------------------------------------------------------------------
#define ASTRIDE 132

template <int ACT>
__global__ __launch_bounds__(256)
void sgemm_kernel(const float* __restrict__ A, const float* __restrict__ Bm,
                  const float* __restrict__ bias, float* __restrict__ C,
                  int M, int N, int K) {
    __shared__ __align__(16) float As[2 * 16 * ASTRIDE];
    __shared__ __align__(16) float Bs[2 * 16 * 128];

    const int tid  = threadIdx.x;
    const int brow = blockIdx.y * 128;
    const int bcol = blockIdx.x * 128;
    const int ty   = tid >> 4;
    const int tx   = tid & 15;
    const int arow = tid >> 1;
    const int acol = (tid & 1) * 8;
    const int br0  = tid >> 5;
    const int bcl  = (tid & 31) * 4;

    const float* Aptr = A  + (size_t)(brow + arow) * K + acol;
    const float* Bptr = Bm + (size_t)br0 * N + bcol + bcl;

    unsigned long long c2[8][4];
#pragma unroll
    for (int m = 0; m < 8; m++)
#pragma unroll
        for (int j = 0; j < 4; j++) c2[m][j] = 0ull;

    float4 a_rg0, a_rg1, b_rg0, b_rg1;
    a_rg0 = *(const float4*)(Aptr + 0);
    a_rg1 = *(const float4*)(Aptr + 4);
    b_rg0 = *(const float4*)(Bptr);
    b_rg1 = *(const float4*)(Bptr + (size_t)8 * N);
    {
        float am[8] = {a_rg0.x, a_rg0.y, a_rg0.z, a_rg0.w,
                       a_rg1.x, a_rg1.y, a_rg1.z, a_rg1.w};
#pragma unroll
        for (int c = 0; c < 8; c++) As[(acol + c) * ASTRIDE + arow] = am[c];
        *(float4*)&Bs[br0 * 128 + bcl]       = b_rg0;
        *(float4*)&Bs[(br0 + 8) * 128 + bcl] = b_rg1;
    }
    __syncthreads();

    int buf = 0;
    const int nblk = K / 16;
    for (int kb = 0; kb < nblk; kb++) {
        const bool has_next = (kb + 1 < nblk);
        if (has_next) {
            const int k0 = (kb + 1) * 16;
            a_rg0 = *(const float4*)(Aptr + k0);
            a_rg1 = *(const float4*)(Aptr + k0 + 4);
            b_rg0 = *(const float4*)(Bptr + (size_t)k0 * N);
            b_rg1 = *(const float4*)(Bptr + (size_t)(k0 + 8) * N);
        }
        const float* Asb = As + buf * 16 * ASTRIDE;
        const float* Bsb = Bs + buf * 16 * 128;
#pragma unroll
        for (int kk = 0; kk < 16; kk++) {
            float4 a0 = *(const float4*)&Asb[kk * ASTRIDE + ty * 8];
            float4 a1 = *(const float4*)&Asb[kk * ASTRIDE + ty * 8 + 4];
            const unsigned long long* brow2 =
                (const unsigned long long*)&Bsb[kk * 128 + tx * 8];
            unsigned long long b2[4];
#pragma unroll
            for (int j = 0; j < 4; j++) b2[j] = brow2[j];
            float am[8] = {a0.x, a0.y, a0.z, a0.w, a1.x, a1.y, a1.z, a1.w};
#pragma unroll
            for (int m = 0; m < 8; m++) {
                unsigned long long aa = pack2(am[m], am[m]);
#pragma unroll
                for (int j = 0; j < 4; j++) c2[m][j] = fma2(aa, b2[j], c2[m][j]);
            }
        }
        if (has_next) {
            float* Asn = As + (buf ^ 1) * 16 * ASTRIDE;
            float* Bsn = Bs + (buf ^ 1) * 16 * 128;
            float am[8] = {a_rg0.x, a_rg0.y, a_rg0.z, a_rg0.w,
                           a_rg1.x, a_rg1.y, a_rg1.z, a_rg1.w};
#pragma unroll
            for (int c = 0; c < 8; c++) Asn[(acol + c) * ASTRIDE + arow] = am[c];
            *(float4*)&Bsn[br0 * 128 + bcl]       = b_rg0;
            *(float4*)&Bsn[(br0 + 8) * 128 + bcl] = b_rg1;
            __syncthreads();
            buf ^= 1;
        }
    }
#pragma unroll
    for (int m = 0; m < 8; m++) {
        const int row = brow + ty * 8 + m;
        float* crow = C + (size_t)row * N + bcol + tx * 8;
#pragma unroll
        for (int j = 0; j < 4; j++) {
            float2 p = unpack2(c2[m][j]);
            const int n = bcol + tx * 8 + 2 * j;
            p.x += bias[n];
            p.y += bias[n + 1];
            if (ACT) { p.x = tanhf(p.x); p.y = tanhf(p.y); }
            *(float2*)&crow[2 * j] = p;
        }
    }
}

// ---------------------------------------------------------------------------
__global__ void fallback_kernel(float* __restrict__ V, const float* __restrict__ noise) {
    __shared__ float rw[8], rn[8];
    const int s = blockIdx.x, t = threadIdx.x;
    const int lane = t & 31, warp = t >> 5;
    float w = V[s * DD + t];
    float n = noise[s * DD + t];
    float pw = w * w, pn = n * n;
#pragma unroll
    for (int off = 16; off > 0; off >>= 1) {
        pw += __shfl_xor_sync(0xffffffffu, pw, off);
        pn += __shfl_xor_sync(0xffffffffu, pn, off);
    }
    if (lane == 0) { rw[warp] = pw; rn[warp] = pn; }
    __syncthreads();
    float sw = 0.f, sn = 0.f;
#pragma unroll
    for (int i = 0; i < 8; i++) { sw += rw[i]; sn += rn[i]; }
    float wn = sqrtf(sw + 1e-24f);
    if (wn < 1e-5f) {
        float nn = sqrtf(sn + 1e-24f);
        V[s * DD + t] = w + n / (nn + 1e-12f) * 1e-4f;
    }
}

// ---------------------------------------------------------------------------
// Trace kernel v6 — HMMA bf16x3. 32 samples/CTA, 128 CTAs, 256 threads.
// Fragment ownership: warp wid owns dims [wid*32, wid*32+32); element (mf,nf,j):
//   sample = mf*16 + r + 8*(j>>1), dim = wid*32 + nf*8 + c2 + (j&1)
// ---------------------------------------------------------------------------
#define AK   264
#define WK   40
#define VROW 260
#define O_ALO 16896
#define O_WB  33792
#define O_V   115712
#define O_XA  148992
#define O_VA  182272
#define O_RA  215552
#define O_RB  216576
#define O_BA  217600
#define O_BB  217728
#define TR_SMEM_BYTES 217856

__device__ __forceinline__ void storeA2(__nv_bfloat16* Ahi, __nv_bfloat16* Alo,
                                        int row, int cc, float f0, float f1) {
    __nv_bfloat16 h0 = __float2bfloat16(f0), h1 = __float2bfloat16(f1);
    __nv_bfloat162 hv; hv.x = h0; hv.y = h1;
    *(__nv_bfloat162*)&Ahi[row * AK + cc] = hv;
    __nv_bfloat162 lv;
    lv.x = __float2bfloat16(f0 - __bfloat162float(h0));
    lv.y = __float2bfloat16(f1 - __bfloat162float(h1));
    *(__nv_bfloat162*)&Alo[row * AK + cc] = lv;
}

__global__ __launch_bounds__(256)
void trace_mma_kernel(const float* __restrict__ Z, const float* __restrict__ V,
                      const __nv_bfloat16* __restrict__ Wbhi,
                      const __nv_bfloat16* __restrict__ Wblo,
                      const __nv_bfloat16* __restrict__ WTbhi,
                      const __nv_bfloat16* __restrict__ WTblo,
                      const float* __restrict__ bp1, const float* __restrict__ wp2,
                      float* __restrict__ mind) {
    extern __shared__ __align__(16) char dsm[];
    __nv_bfloat16* Ahi = (__nv_bfloat16*)(dsm);
    __nv_bfloat16* Alo = (__nv_bfloat16*)(dsm + O_ALO);
    float* v_sm  = (float*)(dsm + O_V);
    float* xa_sm = (float*)(dsm + O_XA);
    float* va_sm = (float*)(dsm + O_VA);
    float* red_a = (float*)(dsm + O_RA);
    float* red_b = (float*)(dsm + O_RB);
    float* bc_a  = (float*)(dsm + O_BA);
    float* bc_b  = (float*)(dsm + O_BB);

    const int tid  = threadIdx.x;
    const int wid  = tid >> 5;
    const int lane = tid & 31;
    const int r    = lane >> 2;
    const int c2   = (lane & 3) * 2;
    const int wn   = wid * 32;
    const int s0   = blockIdx.x * SC;
    const float hs = 1.0f / 15.0f;
    const int wrow = tid >> 2;            // W-chunk load row base
    const int wcol = (tid & 3) * 8;       // W-chunk load col (elems)

    float x[32], vt[32], g[32], d[32];
    float bpr[8], w2r[8];
#pragma unroll
    for (int nf = 0; nf < 4; nf++)
#pragma unroll
        for (int jl = 0; jl < 2; jl++) {
            const int col = wn + nf * 8 + c2 + jl;
            bpr[nf * 2 + jl] = bp1[col];
            w2r[nf * 2 + jl] = wp2[col];
        }

    // init v (cooperative) and x (per-owner float2)
    for (int i = tid; i < SC * DD; i += 256)
        v_sm[(i >> 8) * VROW + (i & 255)] = V[(size_t)(s0 + (i >> 8)) * DD + (i & 255)];
#pragma unroll
    for (int mf = 0; mf < 2; mf++)
#pragma unroll
        for (int nf = 0; nf < 4; nf++)
#pragma unroll
            for (int jp = 0; jp < 2; jp++) {
                const int smp = mf * 16 + r + 8 * jp;
                const int cc = wn + nf * 8 + c2;
                float2 xv = *(const float2*)&Z[(size_t)(s0 + smp) * DD + cc];
                x[mf * 16 + nf * 4 + jp * 2]     = xv.x;
                x[mf * 16 + nf * 4 + jp * 2 + 1] = xv.y;
            }
    float mymin = 3.4e38f;
    __syncthreads();

// matvec: d (zeroed) += A(hi/lo smem) @ B(hi/lo global), K=256 in 8 chunks of 32,
// W chunks double-buffered through smem.
#define MATVEC(BHI, BLO)                                                       \
    do {                                                                       \
        _Pragma("unroll") for (int e = 0; e < 32; e++) d[e] = 0.f;             \
        uint4 rh[4], rl[4];                                                    \
        _Pragma("unroll") for (int p = 0; p < 4; p++) {                        \
            rh[p] = *(const uint4*)((BHI) + (size_t)(p * 64 + wrow) * DD + wcol); \
            rl[p] = *(const uint4*)((BLO) + (size_t)(p * 64 + wrow) * DD + wcol); \
        }                                                                      \
        {                                                                      \
            __nv_bfloat16* wh = (__nv_bfloat16*)(dsm + O_WB);                  \
            __nv_bfloat16* wl = wh + 10240;                                    \
            _Pragma("unroll") for (int p = 0; p < 4; p++) {                    \
                *(uint4*)(wh + (p * 64 + wrow) * WK + wcol) = rh[p];           \
                *(uint4*)(wl + (p * 64 + wrow) * WK + wcol) = rl[p];           \
            }                                                                  \
        }                                                                      \
        _Pragma("unroll 1") for (int c = 0; c < 8; c++) {                      \
            __syncthreads();                                                   \
            if (c < 7) {                                                       \
                const int k0n = (c + 1) * 32;                                  \
                _Pragma("unroll") for (int p = 0; p < 4; p++) {                \
                    rh[p] = *(const uint4*)((BHI) + (size_t)(p * 64 + wrow) * DD + k0n + wcol); \
                    rl[p] = *(const uint4*)((BLO) + (size_t)(p * 64 + wrow) * DD + k0n + wcol); \
                }                                                              \
            }                                                                  \
            const __nv_bfloat16* wbh =                                         \
                (const __nv_bfloat16*)(dsm + O_WB + (c & 1) * 40960);          \
            const __nv_bfloat16* wbl = wbh + 10240;                            \
            const int k0 = c * 32;                                             \
            _Pragma("unroll") for (int kk = 0; kk < 32; kk += 16) {            \
                uint32_t ah[2][4], al[2][4];                                   \
                _Pragma("unroll") for (int mf = 0; mf < 2; mf++) {             \
                    const int mr = mf * 16 + r;                                \
                    ah[mf][0] = *(const uint32_t*)&Ahi[mr * AK + k0 + kk + c2]; \
                    ah[mf][1] = *(const uint32_t*)&Ahi[(mr + 8) * AK + k0 + kk + c2]; \
                    ah[mf][2] = *(const uint32_t*)&Ahi[mr * AK + k0 + kk + c2 + 8]; \
                    ah[mf][3] = *(const uint32_t*)&Ahi[(mr + 8) * AK + k0 + kk + c2 + 8]; \
                    al[mf][0] = *(const uint32_t*)&Alo[mr * AK + k0 + kk + c2]; \
                    al[mf][1] = *(const uint32_t*)&Alo[(mr + 8) * AK + k0 + kk + c2]; \
                    al[mf][2] = *(const uint32_t*)&Alo[mr * AK + k0 + kk + c2 + 8]; \
                    al[mf][3] = *(const uint32_t*)&Alo[(mr + 8) * AK + k0 + kk + c2 + 8]; \
                }                                                              \
                _Pragma("unroll") for (int nf = 0; nf < 4; nf++) {             \
                    const int nb = wn + nf * 8 + r;                            \
                    uint32_t bh[2], bl[2];                                     \
                    bh[0] = *(const uint32_t*)&wbh[nb * WK + kk + c2];         \
                    bh[1] = *(const uint32_t*)&wbh[nb * WK + kk + c2 + 8];     \
                    bl[0] = *(const uint32_t*)&wbl[nb * WK + kk + c2];         \
                    bl[1] = *(const uint32_t*)&wbl[nb * WK + kk + c2 + 8];     \
                    _Pragma("unroll") for (int mf = 0; mf < 2; mf++) {         \
                        mma_bf16(&d[mf * 16 + nf * 4], ah[mf], bh);            \
                        mma_bf16(&d[mf * 16 + nf * 4], ah[mf], bl);            \
                        mma_bf16(&d[mf * 16 + nf * 4], al[mf], bh);            \
                    }                                                          \
                }                                                              \
            }                                                                  \
            if (c < 7) {                                                       \
                __nv_bfloat16* wsh =                                           \
                    (__nv_bfloat16*)(dsm + O_WB + ((c + 1) & 1) * 40960);      \
                __nv_bfloat16* wsl = wsh + 10240;                              \
                _Pragma("unroll") for (int p = 0; p < 4; p++) {                \
                    *(uint4*)(wsh + (p * 64 + wrow) * WK + wcol) = rh[p];      \
                    *(uint4*)(wsl + (p * 64 + wrow) * WK + wcol) = rl[p];      \
                }                                                              \
            }                                                                  \
        }                                                                      \
        __syncthreads();                                                       \
    } while (0)

// ACCEL: xt already in A (hi/lo); vt in regs. Output accel -> g.
#define ACCEL()                                                                \
    do {                                                                       \
        __syncthreads(); /* A(xt) published */                                 \
        MATVEC(WTbhi, WTblo);                                                  \
        _Pragma("unroll") for (int mf = 0; mf < 2; mf++)                       \
        _Pragma("unroll") for (int nf = 0; nf < 4; nf++)                       \
        _Pragma("unroll") for (int jp = 0; jp < 2; jp++) {                     \
            const int e0 = mf * 16 + nf * 4 + jp * 2;                          \
            float h0 = tanhf(d[e0] + bpr[nf * 2]);                             \
            float h1 = tanhf(d[e0 + 1] + bpr[nf * 2 + 1]);                     \
            float sv0 = (1.0f - h0 * h0) * w2r[nf * 2];                        \
            float sv1 = (1.0f - h1 * h1) * w2r[nf * 2 + 1];                    \
            storeA2(Ahi, Alo, mf * 16 + r + 8 * jp, wn + nf * 8 + c2, sv0, sv1); \
        }                                                                      \
        __syncthreads();                                                       \
        MATVEC(Wbhi, Wblo);                                                    \
        {                                                                      \
            float pg[4] = {0.f, 0.f, 0.f, 0.f};                                \
            float pv[4] = {0.f, 0.f, 0.f, 0.f};                                \
            _Pragma("unroll") for (int mf = 0; mf < 2; mf++)                   \
            _Pragma("unroll") for (int nf = 0; nf < 4; nf++)                   \
            _Pragma("unroll") for (int j = 0; j < 4; j++) {                    \
                const int e = mf * 16 + nf * 4 + j;                            \
                const int sl = mf * 2 + (j >> 1);                              \
                pg[sl] += d[e] * vt[e];                                        \
                pv[sl] += vt[e] * vt[e];                                       \
            }                                                                  \
            _Pragma("unroll") for (int sl = 0; sl < 4; sl++) {                 \
                pg[sl] += __shfl_xor_sync(0xffffffffu, pg[sl], 1);             \
                pg[sl] += __shfl_xor_sync(0xffffffffu, pg[sl], 2);             \
                pv[sl] += __shfl_xor_sync(0xffffffffu, pv[sl], 1);             \
                pv[sl] += __shfl_xor_sync(0xffffffffu, pv[sl], 2);             \
            }                                                                  \
            if ((lane & 3) == 0) {                                             \
                _Pragma("unroll") for (int sl = 0; sl < 4; sl++) {             \
                    const int row = (sl >> 1) * 16 + r + 8 * (sl & 1);         \
                    red_a[wid * 32 + row] = pg[sl];                            \
                    red_b[wid * 32 + row] = pv[sl];                            \
                }                                                              \
            }                                                                  \
        }                                                                      \
        __syncthreads();                                                       \
        if (tid < 32) {                                                        \
            float sg = 0.f;                                                    \
            float sv2 = 0.f;                                                   \
            _Pragma("unroll") for (int w8 = 0; w8 < 8; w8++) {                 \
                sg += red_a[w8 * 32 + tid];                                    \
                sv2 += red_b[w8 * 32 + tid];                                   \
            }                                                                  \
            bc_a[tid] = sg;                                                    \
            bc_b[tid] = sv2;                                                   \
        }                                                                      \
        __syncthreads();                                                       \
        _Pragma("unroll") for (int mf = 0; mf < 2; mf++)                       \
        _Pragma("unroll") for (int nf = 0; nf < 4; nf++)                       \
        _Pragma("unroll") for (int j = 0; j < 4; j++) {                        \
            const int e = mf * 16 + nf * 4 + j;                                \
            const int smp = mf * 16 + r + 8 * (j >> 1);                        \
            g[e] = 0.5f * bc_b[smp] * d[e] - bc_a[smp] * vt[e];                \
        }                                                                      \
    } while (0)

// Variadic so the body may contain top-level commas.
#define FOR_PAIR(...)                                                          \
    _Pragma("unroll") for (int mf = 0; mf < 2; mf++)                           \
    _Pragma("unroll") for (int nf = 0; nf < 4; nf++)                           \
    _Pragma("unroll") for (int jp = 0; jp < 2; jp++) {                         \
        const int e0 = mf * 16 + nf * 4 + jp * 2;                              \
        const int row = mf * 16 + r + 8 * jp;                                  \
        const int cc = wn + nf * 8 + c2;                                       \
        const int vidx = row * VROW + cc;                                      \
        (void)e0; (void)row; (void)cc; (void)vidx;                             \
        __VA_ARGS__                                                            \
    }

    for (int step = 0; step < NSTEP; step++) {
        // ---- stage 1: vt = v; xt = x
        FOR_PAIR({
            float2 vv = *(float2*)&v_sm[vidx];
            vt[e0] = vv.x; vt[e0 + 1] = vv.y;
            storeA2(Ahi, Alo, row, cc, x[e0], x[e0 + 1]);
        })
        ACCEL();
        FOR_PAIR({
            float2 t0; t0.x = vt[e0]; t0.y = vt[e0 + 1];
            *(float2*)&xa_sm[vidx] = t0;
            float2 t1; t1.x = g[e0]; t1.y = g[e0 + 1];
            *(float2*)&va_sm[vidx] = t1;
        })
        // ---- stage 2: xt = x + h/2*v (vt==v); vt = v + h/2*g1
        FOR_PAIR({
            storeA2(Ahi, Alo, row, cc,
                    x[e0] + 0.5f * hs * vt[e0], x[e0 + 1] + 0.5f * hs * vt[e0 + 1]);
            vt[e0]     += 0.5f * hs * g[e0];
            vt[e0 + 1] += 0.5f * hs * g[e0 + 1];
        })
        ACCEL();
        FOR_PAIR({
            float2 xv = *(float2*)&xa_sm[vidx];
            xv.x += 2.0f * vt[e0]; xv.y += 2.0f * vt[e0 + 1];
            *(float2*)&xa_sm[vidx] = xv;
            float2 av = *(float2*)&va_sm[vidx];
            av.x += 2.0f * g[e0]; av.y += 2.0f * g[e0 + 1];
            *(float2*)&va_sm[vidx] = av;
        })
        // ---- stage 3: xt = x + h/2*vt2; vt = v + h/2*g2
        FOR_PAIR({
            storeA2(Ahi, Alo, row, cc,
                    x[e0] + 0.5f * hs * vt[e0], x[e0 + 1] + 0.5f * hs * vt[e0 + 1]);
            float2 vv = *(float2*)&v_sm[vidx];
            vt[e0]     = vv.x + 0.5f * hs * g[e0];
            vt[e0 + 1] = vv.y + 0.5f * hs * g[e0 + 1];
        })
        ACCEL();
        FOR_PAIR({
            float2 xv = *(float2*)&xa_sm[vidx];
            xv.x += 2.0f * vt[e0]; xv.y += 2.0f * vt[e0 + 1];
            *(float2*)&xa_sm[vidx] = xv;
            float2 av = *(float2*)&va_sm[vidx];
            av.x += 2.0f * g[e0]; av.y += 2.0f * g[e0 + 1];
            *(float2*)&va_sm[vidx] = av;
        })
        // ---- stage 4: xt = x + h*vt3; vt = v + h*g3
        FOR_PAIR({
            storeA2(Ahi, Alo, row, cc,
                    x[e0] + hs * vt[e0], x[e0 + 1] + hs * vt[e0 + 1]);
            float2 vv = *(float2*)&v_sm[vidx];
            vt[e0]     = vv.x + hs * g[e0];
            vt[e0 + 1] = vv.y + hs * g[e0 + 1];
        })
        ACCEL();
        // ---- final update + distance partials
        {
            float pd[4] = {0.f, 0.f, 0.f, 0.f};
            FOR_PAIR({
                float2 xav = *(float2*)&xa_sm[vidx];
                float2 vav = *(float2*)&va_sm[vidx];
                float2 vv  = *(float2*)&v_sm[vidx];
                x[e0]     += (hs / 6.0f) * (xav.x + vt[e0]);
                x[e0 + 1] += (hs / 6.0f) * (xav.y + vt[e0 + 1]);
                vv.x += (hs / 6.0f) * (vav.x + g[e0]);
                vv.y += (hs / 6.0f) * (vav.y + g[e0 + 1]);
                *(float2*)&v_sm[vidx] = vv;
                float2 zev = *(const float2*)&Z[(size_t)(NB + s0 + row) * DD + cc];
                float dd0 = x[e0] - zev.x;
                float dd1 = x[e0 + 1] - zev.y;
                pd[mf * 2 + jp] += dd0 * dd0 + dd1 * dd1;
            })
#pragma unroll
            for (int sl = 0; sl < 4; sl++) {
                pd[sl] += __shfl_xor_sync(0xffffffffu, pd[sl], 1);
                pd[sl] += __shfl_xor_sync(0xffffffffu, pd[sl], 2);
            }
            if ((lane & 3) == 0) {
#pragma unroll
                for (int sl = 0; sl < 4; sl++) {
                    const int row = (sl >> 1) * 16 + r + 8 * (sl & 1);
                    red_a[wid * 32 + row] = pd[sl];
                }
            }
            __syncthreads();
            if (tid < 32) {
                float tot = 0.f;
#pragma unroll
                for (int w8 = 0; w8 < 8; w8++) tot += red_a[w8 * 32 + tid];
                mymin = fminf(mymin, tot);
            }
            __syncthreads();
        }
    }

    if (tid < 32) mind[s0 + tid] = mymin;
#undef FOR_PAIR
#undef ACCEL
#undef MATVEC
}

// ---------------------------------------------------------------------------
__global__ void reduce_kernel(const float* __restrict__ mind, float* __restrict__ out) {
    __shared__ float sm[1024];
    const int t = threadIdx.x;
    float a = mind[t] + mind[t + 1024] + mind[t + 2048] + mind[t + 3072];
    sm[t] = a;
    __syncthreads();
    for (int off = 512; off > 0; off >>= 1) {
        if (t < off) sm[t] += sm[t + off];
        __syncthreads();
    }
    if (t == 0) out[0] = sm[0] * (1.0f / (float)NB);
}

// ---------------------------------------------------------------------------
// Launch
// ---------------------------------------------------------------------------
extern "C" void kernel_launch(void* const* d_in, const int* in_sizes, int n_in,
                              void* d_out, int out_size) {
    const float* x_start = (const float*)d_in[0];
    const float* x_end   = (const float*)d_in[1];
    const float* noise   = (const float*)d_in[2];
    const float* W1  = (const float*)d_in[3];
    const float* b1  = (const float*)d_in[4];
    const float* W2  = (const float*)d_in[5];
    const float* b2  = (const float*)d_in[6];
    const float* Ww1 = (const float*)d_in[7];
    const float* bw1 = (const float*)d_in[8];
    const float* Ww2 = (const float*)d_in[9];
    const float* bw2 = (const float*)d_in[10];
    const float* Wp1 = (const float*)d_in[11];
    const float* bp1 = (const float*)d_in[12];
    const float* wp2 = (const float*)d_in[13];

    float *Hb, *Zb, *HWb, *Vb, *Md;
    cudaGetSymbolAddress((void**)&Hb,  g_H);
    cudaGetSymbolAddress((void**)&Zb,  g_Z);
    cudaGetSymbolAddress((void**)&HWb, g_HW);
    cudaGetSymbolAddress((void**)&Vb,  g_V);
    cudaGetSymbolAddress((void**)&Md,  g_mind);
    __nv_bfloat16 *Xhi, *Xlo, *Whi, *Wlo, *Wph, *Wpl, *WTh, *WTl;
    cudaGetSymbolAddress((void**)&Xhi, g_Xhi);
    cudaGetSymbolAddress((void**)&Xlo, g_Xlo);
    cudaGetSymbolAddress((void**)&Whi, g_W1Thi);
    cudaGetSymbolAddress((void**)&Wlo, g_W1Tlo);
    cudaGetSymbolAddress((void**)&Wph, g_Wbhi);
    cudaGetSymbolAddress((void**)&Wpl, g_Wblo);
    cudaGetSymbolAddress((void**)&WTh, g_WTbhi);
    cudaGetSymbolAddress((void**)&WTl, g_WTblo);

    cudaFuncSetAttribute(trace_mma_kernel,
                         cudaFuncAttributeMaxDynamicSharedMemorySize,
                         TR_SMEM_BYTES);

    // conversions
    convX_kernel<<<(2 * NB * DIN / 4) / 256, 256>>>(x_start, x_end, Xhi, Xlo);
    convW_kernel<<<dim3(HH / 32, DIN / 32), dim3(32, 32)>>>(W1, Whi, Wlo);
    prepW_kernel<<<DD, DD>>>(Wp1, Wph, Wpl, WTh, WTl);
    // enc1 on tensor cores
    enc1_mma_kernel<<<dim3(HH / 128, 2 * NB / 128), 256>>>(
        Xhi, Xlo, Whi, Wlo, b1, Hb);
    // enc2 + winds (fp32 SGEMM)
    sgemm_kernel<0><<<dim3(DD / 128, 2 * NB / 128), 256>>>(Hb, W2, b2, Zb, 2 * NB, DD, HH);
    sgemm_kernel<1><<<dim3(DD / 128, NB / 128), 256>>>(Zb,  Ww1, bw1, HWb, NB, DD, DD);
    sgemm_kernel<0><<<dim3(DD / 128, NB / 128), 256>>>(HWb, Ww2, bw2, Vb,  NB, DD, DD);
    fallback_kernel<<<NB, DD>>>(Vb, noise);
    // trace on tensor cores
    trace_mma_kernel<<<NB / SC, 256, TR_SMEM_BYTES>>>(
        Zb, Vb, Wph, Wpl, WTh, WTl, bp1, wp2, Md);
    reduce_kernel<<<1, 1024>>>(Md, (float*)d_out);
}